// round 7
// baseline (speedup 1.0000x reference)
#include <cuda_runtime.h>
#include <math.h>

#define S_MAX   360
#define EPS_CLP 1e-6f
#define FULL    0xFFFFFFFFu
#define SPW     8          // samples per warp
#define NWARP   8          // warps per block
#define SPB     (SPW * NWARP)   // 64 samples per block

// dot(u, qua_mul(y, q)) == v . q  with v = M(y)^T u (M orthogonal).
// Combined argmin over concat([acos(d), acos(-d)]) == argmax over |d| with
// tie order: half0 (d>=0) before half1, lowest symmetry index first. Clamp is
// applied to the final acos argument; per-element clamp only matters when two
// distinct dots both exceed 1-eps in one sample (measure-zero here).

__device__ __forceinline__ void compute_v(const float4 xv, const float4 yv,
                                          float& vx, float& vy, float& vz, float& vw)
{
    const float inv = rsqrtf(xv.x*xv.x + xv.y*xv.y + xv.z*xv.z + xv.w*xv.w);
    const float ux = xv.x*inv, uy = xv.y*inv, uz = xv.z*inv, uw = xv.w*inv;
    const float px = yv.x, py = yv.y, pz = yv.z, pw = yv.w;
    vx =  ux*pw - uy*pz + uz*py - uw*px;
    vy =  ux*pz + uy*pw - uz*px - uw*py;
    vz = -ux*py + uy*px + uz*pw - uw*pz;
    vw =  ux*px + uy*py + uz*pz + uw*pw;
}

__device__ __forceinline__ void write_result(float* __restrict__ out, int B, int b,
                                             const float4 xv, const float4 yv,
                                             const float4 q, float vbest, bool half0)
{
    const float loss = acosf(vbest);
    const float px = yv.x, py = yv.y, pz = yv.z, pw = yv.w;
    const float qx = q.x,  qy = q.y,  qz = q.z,  qw = q.w;
    const float rw = qw*pw - qx*px - qy*py - qz*pz;
    const float rx = qw*px + qx*pw + qy*pz - qz*py;
    const float ry = qw*py - qx*pz + qy*pw + qz*px;
    const float rz = qw*pz + qx*py - qy*px + qz*pw;
    const float sgn = half0 ? 1.0f : -1.0f;
    out[b] = loss;
    reinterpret_cast<float4*>(out + B)[b]   = make_float4(xv.x*sgn, xv.y*sgn, xv.z*sgn, xv.w*sgn);
    reinterpret_cast<float4*>(out + 5*B)[b] = make_float4(rx, ry, rz, rw);
}

__global__ __launch_bounds__(256, 4)   // <=64 regs -> 32 warps/SM
void quer_loss_kernel(const float*  __restrict__ x,
                      const float*  __restrict__ y,
                      const int*    __restrict__ n,
                      const float4* __restrict__ sym,   // [5*360] float4
                      float* __restrict__ out, int B)
{
    __shared__ float4 s4[S_MAX];     // class-4 table (5.76 KB)
    __shared__ float4 ss[4 * 12];    // classes 0..3, 12 entries each
    __shared__ int    queue[SPB];    // class-4 sample indices in this block
    __shared__ int    cnt;

    const int tid  = threadIdx.x;
    const int lane = tid & 31;
    const int warp = tid >> 5;

    if (tid == 0) cnt = 0;
    for (int i = tid; i < S_MAX; i += 256)
        s4[i] = __ldg(sym + 4 * S_MAX + i);
    if (tid < 48)
        ss[tid] = __ldg(sym + (tid / 12) * S_MAX + (tid % 12));
    __syncthreads();

    const int base = blockIdx.x * SPB + warp * SPW;
    const int o = lane & 7;          // owned-sample slot
    const int g = lane >> 3;         // group 0..3 handles entries 3g..3g+2
    const int b = base + o;
    const bool valid = (b < B);
    const int bl = valid ? b : (B - 1);

    const float4 xv = __ldg(reinterpret_cast<const float4*>(x) + bl);
    const float4 yv = __ldg(reinterpret_cast<const float4*>(y) + bl);
    const int cls   = __ldg(n + bl);

    // collect class-4 samples into the block queue (one push per sample)
    if (valid && lane < SPW && cls == 4) {
        const int p = atomicAdd(&cnt, 1);
        queue[p] = b;
    }

    // ---- small-class phase: 4 lanes per sample, 3 entries per lane ----
    {
        float vx, vy, vz, vw;
        compute_v(xv, yv, vx, vy, vz, vw);

        float best0 = -2.0f, best1 = -2.0f;
        int   i0 = 0, i1 = 0;
        if (cls != 4) {
            const int c = (cls == 0) ? 1 : (cls == 1) ? 2 : (cls == 2) ? 4 : 12;
            #pragma unroll
            for (int k = 0; k < 3; ++k) {
                const int s = g * 3 + k;
                if (s < c) {
                    const float4 q = ss[cls * 12 + s];
                    float d = vx*q.x + vy*q.y + vz*q.z + vw*q.w;
                    d = fminf(fmaxf(d, -1.0f + EPS_CLP), 1.0f - EPS_CLP);
                    if ( d > best0) { best0 =  d; i0 = s; }
                    if (-d > best1) { best1 = -d; i1 = s; }
                }
            }
        }
        #pragma unroll
        for (int off = 8; off < 32; off <<= 1) {
            const float t0 = __shfl_xor_sync(FULL, best0, off);
            const int   k0 = __shfl_xor_sync(FULL, i0,    off);
            if (t0 > best0 || (t0 == best0 && k0 < i0)) { best0 = t0; i0 = k0; }
            const float t1 = __shfl_xor_sync(FULL, best1, off);
            const int   k1 = __shfl_xor_sync(FULL, i1,    off);
            if (t1 > best1 || (t1 == best1 && k1 < i1)) { best1 = t1; i1 = k1; }
        }
        if (valid && lane < SPW && cls != 4) {
            const bool  half0 = (best0 >= best1);
            const float vbest = half0 ? best0 : best1;
            const int   sbest = half0 ? i0 : i1;
            write_result(out, B, b, xv, yv, ss[cls * 12 + sbest], vbest, half0);
        }
    }

    __syncthreads();                 // queue ready
    const int c4 = cnt;

    // ---- cooperative phase: warps pull balanced work from the queue ----
    for (int i = warp; i < c4; i += NWARP) {
        const int sb = queue[i];     // smem broadcast

        const float4 xs = __ldg(reinterpret_cast<const float4*>(x) + sb);
        const float4 ys = __ldg(reinterpret_cast<const float4*>(y) + sb);
        float wvx, wvy, wvz, wvw;
        compute_v(xs, ys, wvx, wvy, wvz, wvw);   // uniform across lanes

        // pass 1: dots + max|d| (two chains for ILP); no predication
        float dreg[12];
        float m0 = 0.0f, m1 = 0.0f;
        #pragma unroll
        for (int k = 0; k < 12; ++k) {
            const int s = lane + k * 32;
            const float4 q = s4[(s < S_MAX) ? s : (S_MAX - 1)];  // dup is masked below
            const float d = wvx*q.x + wvy*q.y + wvz*q.z + wvw*q.w;
            dreg[k] = d;
            const float a = fabsf(d);
            if (k & 1) m1 = fmaxf(m1, a); else m0 = fmaxf(m0, a);
        }
        const float mm = fmaxf(m0, m1);
        const int   M  = __reduce_max_sync(FULL, __float_as_int(mm));  // mm>=0: bits are order-preserving
        const float Mf = __int_as_float(M);

        // pass 2: min concatenated position among elements matching the max
        int pos = 0x7fffffff;
        #pragma unroll
        for (int k = 0; k < 12; ++k) {
            const int s = lane + k * 32;
            if (s < S_MAX && fabsf(dreg[k]) == Mf) {
                const int p = s + ((dreg[k] < 0.0f) ? S_MAX : 0);  // half1 after half0
                pos = min(pos, p);
            }
        }
        pos = __reduce_min_sync(FULL, pos);

        const bool  half0 = (pos < S_MAX);
        const int   sbest = half0 ? pos : (pos - S_MAX);
        const float vbest = fminf(Mf, 1.0f - EPS_CLP);   // clamp only the acos arg

        if (lane == 0)
            write_result(out, B, sb, xs, ys, s4[sbest], vbest, half0);
    }
}

extern "C" void kernel_launch(void* const* d_in, const int* in_sizes, int n_in,
                              void* d_out, int out_size)
{
    // metadata order: x[B,4], y[B,4], pred_n[B,5] (unused), n[B],
    //                 sym_qua[5,360,4], sym_mask[5,360] (unused)
    const float*  x   = (const float*) d_in[0];
    const float*  y   = (const float*) d_in[1];
    const int*    n   = (const int*)   d_in[3];
    const float4* sym = (const float4*)d_in[4];
    float* out = (float*)d_out;

    const int B = in_sizes[3];                    // 65536
    const int blocks = (B + SPB - 1) / SPB;       // 1024
    quer_loss_kernel<<<blocks, 256>>>(x, y, n, sym, out, B);
}

// round 8
// speedup vs baseline: 1.1322x; 1.1322x over previous
#include <cuda_runtime.h>
#include <math.h>

#define S_MAX   360
#define EPS_CLP 1e-6f
#define FULL    0xFFFFFFFFu
#define SPW     16                 // samples per warp (lanes 0..15 own one)
#define NWARP   8                  // warps per block
#define SPB     (SPW * NWARP)      // 128 samples per block

// dot(u, qua_mul(y, q)) == v . q  with v = M(y)^T u (M orthogonal).
// Combined argmin over concat([acos(d), acos(-d)]) == argmax over |d| with
// tie order: half0 (d>=0) before half1, lowest symmetry index first.

__device__ __forceinline__ void compute_v(const float4 xv, const float4 yv,
                                          float& vx, float& vy, float& vz, float& vw)
{
    const float inv = rsqrtf(xv.x*xv.x + xv.y*xv.y + xv.z*xv.z + xv.w*xv.w);
    const float ux = xv.x*inv, uy = xv.y*inv, uz = xv.z*inv, uw = xv.w*inv;
    const float px = yv.x, py = yv.y, pz = yv.z, pw = yv.w;
    vx =  ux*pw - uy*pz + uz*py - uw*px;
    vy =  ux*pz + uy*pw - uz*px - uw*py;
    vz = -ux*py + uy*px + uz*pw - uw*pz;
    vw =  ux*px + uy*py + uz*pz + uw*pw;
}

__device__ __forceinline__ void write_result(float* __restrict__ out, int B, int b,
                                             const float4 xv, const float4 yv,
                                             const float4 q, float vbest, bool half0)
{
    const float loss = acosf(vbest);
    const float px = yv.x, py = yv.y, pz = yv.z, pw = yv.w;
    const float qx = q.x,  qy = q.y,  qz = q.z,  qw = q.w;
    const float rw = qw*pw - qx*px - qy*py - qz*pz;
    const float rx = qw*px + qx*pw + qy*pz - qz*py;
    const float ry = qw*py - qx*pz + qy*pw + qz*px;
    const float rz = qw*pz + qx*py - qy*px + qz*pw;
    const float sgn = half0 ? 1.0f : -1.0f;
    out[b] = loss;
    reinterpret_cast<float4*>(out + B)[b]   = make_float4(xv.x*sgn, xv.y*sgn, xv.z*sgn, xv.w*sgn);
    reinterpret_cast<float4*>(out + 5*B)[b] = make_float4(rx, ry, rz, rw);
}

__global__ __launch_bounds__(256, 4)
void quer_loss_kernel(const float*  __restrict__ x,
                      const float*  __restrict__ y,
                      const int*    __restrict__ n,
                      const float4* __restrict__ sym,   // [5*360] float4
                      float* __restrict__ out, int B)
{
    __shared__ float4 s4[S_MAX];     // class-4 table (5.76 KB)
    __shared__ float4 ss[4 * 12];    // classes 0..3, 12 entries each
    __shared__ int    qb [SPB];      // queued sample index
    __shared__ float4 qx4[SPB];      // queued xv
    __shared__ float4 qy4[SPB];      // queued yv
    __shared__ float4 qv4[SPB];      // queued v
    __shared__ int    cnt;

    const int tid  = threadIdx.x;
    const int lane = tid & 31;
    const int warp = tid >> 5;

    if (tid == 0) cnt = 0;
    for (int i = tid; i < S_MAX; i += 256)
        s4[i] = __ldg(sym + 4 * S_MAX + i);
    if (tid < 48)
        ss[tid] = __ldg(sym + (tid / 12) * S_MAX + (tid % 12));
    __syncthreads();

    const int base = blockIdx.x * SPB + warp * SPW;
    const int o = lane & 15;         // owned-sample slot within warp
    const int g = lane >> 4;         // group 0/1 handles entries 6g..6g+5
    const int b = base + o;
    const bool valid = (b < B);
    const int bl = valid ? b : (B - 1);

    const float4 xv = __ldg(reinterpret_cast<const float4*>(x) + bl);
    const float4 yv = __ldg(reinterpret_cast<const float4*>(y) + bl);
    const int cls   = __ldg(n + bl);

    float vx, vy, vz, vw;
    compute_v(xv, yv, vx, vy, vz, vw);

    // enqueue class-4 samples with their precomputed operands
    if (valid && lane < SPW && cls == 4) {
        const int p = atomicAdd(&cnt, 1);
        qb [p] = b;
        qx4[p] = xv;
        qy4[p] = yv;
        qv4[p] = make_float4(vx, vy, vz, vw);
    }

    // ---- small-class phase: 2 lanes per sample, 6 entries per lane ----
    {
        float best0 = -2.0f, best1 = -2.0f;
        int   i0 = 0, i1 = 0;
        if (cls != 4) {
            const int c = (cls == 0) ? 1 : (cls == 1) ? 2 : (cls == 2) ? 4 : 12;
            #pragma unroll
            for (int k = 0; k < 6; ++k) {
                const int s = g * 6 + k;
                if (s < c) {
                    const float4 q = ss[cls * 12 + s];
                    float d = vx*q.x + vy*q.y + vz*q.z + vw*q.w;
                    d = fminf(fmaxf(d, -1.0f + EPS_CLP), 1.0f - EPS_CLP);
                    if ( d > best0) { best0 =  d; i0 = s; }   // strict > keeps lowest s
                    if (-d > best1) { best1 = -d; i1 = s; }
                }
            }
        }
        // combine the two group-lanes of each sample (xor 16)
        {
            const float t0 = __shfl_xor_sync(FULL, best0, 16);
            const int   k0 = __shfl_xor_sync(FULL, i0,    16);
            if (t0 > best0 || (t0 == best0 && k0 < i0)) { best0 = t0; i0 = k0; }
            const float t1 = __shfl_xor_sync(FULL, best1, 16);
            const int   k1 = __shfl_xor_sync(FULL, i1,    16);
            if (t1 > best1 || (t1 == best1 && k1 < i1)) { best1 = t1; i1 = k1; }
        }
        if (valid && lane < SPW && cls != 4) {
            const bool  half0 = (best0 >= best1);
            const float vbest = half0 ? best0 : best1;
            const int   sbest = half0 ? i0 : i1;
            write_result(out, B, b, xv, yv, ss[cls * 12 + sbest], vbest, half0);
        }
    }

    __syncthreads();                 // queue ready
    const int c4 = cnt;

    // ---- cooperative phase: warps pull balanced work from the queue ----
    for (int i = warp; i < c4; i += NWARP) {
        const int sb = qb[i];                    // uniform smem broadcasts
        const float4 xs = qx4[i];
        const float4 ys = qy4[i];
        const float4 vv = qv4[i];
        const float wvx = vv.x, wvy = vv.y, wvz = vv.z, wvw = vv.w;

        // pass 1: dots + max|d| (two chains for ILP); no predication
        float dreg[12];
        float m0 = 0.0f, m1 = 0.0f;
        #pragma unroll
        for (int k = 0; k < 12; ++k) {
            const int s = lane + k * 32;
            const float4 q = s4[(s < S_MAX) ? s : (S_MAX - 1)];  // dup masked in pass 2
            const float d = wvx*q.x + wvy*q.y + wvz*q.z + wvw*q.w;
            dreg[k] = d;
            const float a = fabsf(d);
            if (k & 1) m1 = fmaxf(m1, a); else m0 = fmaxf(m0, a);
        }
        const float mm = fmaxf(m0, m1);
        const int   M  = __reduce_max_sync(FULL, __float_as_int(mm));  // mm>=0: order-preserving bits
        const float Mf = __int_as_float(M);

        // pass 2: min concatenated position among elements matching the max
        int pos = 0x7fffffff;
        #pragma unroll
        for (int k = 0; k < 12; ++k) {
            const int s = lane + k * 32;
            if (s < S_MAX && fabsf(dreg[k]) == Mf) {
                const int p = s + ((dreg[k] < 0.0f) ? S_MAX : 0);  // half1 after half0
                pos = min(pos, p);
            }
        }
        pos = __reduce_min_sync(FULL, pos);

        const bool  half0 = (pos < S_MAX);
        const int   sbest = half0 ? pos : (pos - S_MAX);
        const float vbest = fminf(Mf, 1.0f - EPS_CLP);   // clamp only the acos arg

        if (lane == 0)
            write_result(out, B, sb, xs, ys, s4[sbest], vbest, half0);
    }
}

extern "C" void kernel_launch(void* const* d_in, const int* in_sizes, int n_in,
                              void* d_out, int out_size)
{
    // metadata order: x[B,4], y[B,4], pred_n[B,5] (unused), n[B],
    //                 sym_qua[5,360,4], sym_mask[5,360] (unused)
    const float*  x   = (const float*) d_in[0];
    const float*  y   = (const float*) d_in[1];
    const int*    n   = (const int*)   d_in[3];
    const float4* sym = (const float4*)d_in[4];
    float* out = (float*)d_out;

    const int B = in_sizes[3];                    // 65536
    const int blocks = (B + SPB - 1) / SPB;       // 512
    quer_loss_kernel<<<blocks, 256>>>(x, y, n, sym, out, B);
}